// round 3
// baseline (speedup 1.0000x reference)
#include <cuda_runtime.h>
#include <cuda_fp16.h>
#include <cstdint>

#define NCTA 128
#define TPB  512
#define HDIM 1024

// Exchange: one u64 per h-pair = {tag:32 | fp16 h[2s+1] : fp16 h[2s]}
__device__ unsigned long long g_hpack[2][HDIM / 2];
__device__ float g_xg[4 * HDIM];

// ---------------- PTX helpers ----------------
__device__ __forceinline__ unsigned long long ld_relaxed_u64(const unsigned long long* p) {
    unsigned long long v;
    asm volatile("ld.relaxed.gpu.global.u64 %0, [%1];" : "=l"(v) : "l"(p));
    return v;
}
__device__ __forceinline__ void st_relaxed_u64(unsigned long long* p, unsigned long long v) {
    asm volatile("st.relaxed.gpu.global.u64 [%0], %1;" :: "l"(p), "l"(v) : "memory");
}
__device__ __forceinline__ unsigned long long lds_vol_u64(unsigned a) {
    unsigned long long v;
    asm volatile("ld.volatile.shared.u64 %0, [%1];" : "=l"(v) : "r"(a));
    return v;
}
__device__ __forceinline__ void sts_vol_u64(unsigned a, unsigned long long v) {
    asm volatile("st.volatile.shared.u64 [%0], %1;" :: "r"(a), "l"(v));
}
__device__ __forceinline__ unsigned long long fma2(unsigned long long a, unsigned long long b,
                                                   unsigned long long c) {
    unsigned long long d;
    asm("fma.rn.f32x2 %0, %1, %2, %3;" : "=l"(d) : "l"(a), "l"(b), "l"(c));
    return d;
}
__device__ __forceinline__ void lds_v2_u64(unsigned addr, unsigned long long& a,
                                           unsigned long long& b) {
    asm volatile("ld.shared.v2.u64 {%0, %1}, [%2];" : "=l"(a), "=l"(b) : "r"(addr));
}
__device__ __forceinline__ float f2sum(unsigned long long v) {
    return __uint_as_float((unsigned)v) + __uint_as_float((unsigned)(v >> 32));
}
__device__ __forceinline__ float sigf(float x) { return 1.0f / (1.0f + __expf(-x)); }
__device__ __forceinline__ float tanh_acc(float x) {
    float e = __expf(2.0f * x);
    return 1.0f - 2.0f / (e + 1.0f);
}

// ---------------- x_gates = x @ W_ih.T + b_ih + b_hh ----------------
__global__ void xgates_kernel(const float* __restrict__ x, const float* __restrict__ Wih,
                              const float* __restrict__ bih, const float* __restrict__ bhh) {
    int lane = threadIdx.x & 31;
    int row  = blockIdx.x * 8 + (threadIdx.x >> 5);
    const float4* wr = (const float4*)(Wih + (size_t)row * HDIM);
    const float4* xr = (const float4*)x;
    float acc = 0.f;
    #pragma unroll
    for (int i = 0; i < 8; i++) {
        float4 w4 = wr[i * 32 + lane];
        float4 x4 = xr[i * 32 + lane];
        acc += w4.x * x4.x + w4.y * x4.y + w4.z * x4.z + w4.w * x4.w;
    }
    #pragma unroll
    for (int off = 16; off; off >>= 1) acc += __shfl_xor_sync(0xffffffffu, acc, off);
    if (lane == 0) g_xg[row] = acc + bih[row] + bhh[row];
}

// ---------------- persistent LSTM rollout ----------------
// 128 CTAs x 512 threads. CTA owns h elems [8c, 8c+8) -> 32 gate rows.
// Warp w: rowgroup rg=w>>1 (4 rows), h-slice sl=w&1 (512 elems).
// Lane l covers h[sl*512 + j*128 + 4l .. +3] for j=0..3 (conflict-free LDS.128).
// Per-row per-slice partials meet in tagged SMEM words (no 2nd barrier).
__global__ void __launch_bounds__(TPB, 1)
lstm_kernel(const float* __restrict__ Whh, float* __restrict__ out, int N) {
    __shared__ float h_sm[2][HDIM];                 // double buffer, 8KB
    __shared__ unsigned long long g_part[2][32];    // [slice][local row] tagged partials

    const int tid  = threadIdx.x;
    const int lane = tid & 31;
    const int warp = tid >> 5;
    const int cta  = blockIdx.x;
    const int rg   = warp >> 1;
    const int sl   = warp & 1;

    // Pin weights: 4 rows x 4 j-chunks x 4 floats/lane = 64 regs.
    ulonglong2 w[4][4];
    #pragma unroll
    for (int r = 0; r < 4; r++) {
        int rl   = rg * 4 + r;
        int grow = (rl >> 3) * HDIM + cta * 8 + (rl & 7);
        const float* base = Whh + (size_t)grow * HDIM + sl * 512 + 4 * lane;
        #pragma unroll
        for (int j = 0; j < 4; j++)
            w[r][j] = *(const ulonglong2*)(base + j * 128);
    }

    // Epilogue threads preload their 4 gate biases (x-contribution).
    float xg4[4] = {0.f, 0.f, 0.f, 0.f};
    if (tid < 8) {
        #pragma unroll
        for (int g = 0; g < 4; g++) xg4[g] = g_xg[g * HDIM + cta * 8 + tid];
    }

    if (tid < 64) ((unsigned long long*)g_part)[tid] = 0ull;  // tag 0 != any t+1

    const unsigned hbase = (unsigned)__cvta_generic_to_shared(&h_sm[0][0]);
    const unsigned gpbase = (unsigned)__cvta_generic_to_shared(&g_part[0][0]);

    float c_state = 0.f;  // live in tid<8

    for (int t = 0; t < N; t++) {
        const int buf = t & 1;

        // ---- acquire h(t): single tagged u64 poll per thread ----
        if (t == 0) {
            *(float2*)&h_sm[0][2 * tid] = make_float2(0.f, 0.f);
        } else {
            const unsigned long long* bp = g_hpack[buf];
            const unsigned tag = (unsigned)t;
            unsigned long long v = ld_relaxed_u64(bp + tid);
            while ((unsigned)(v >> 32) != tag) v = ld_relaxed_u64(bp + tid);
            unsigned lo = (unsigned)v;
            __half2 hh = *(__half2*)&lo;
            float2 f2 = __half22float2(hh);
            *(float2*)&h_sm[buf][2 * tid] = f2;
        }
        __syncthreads();   // the only barrier per step

        // ---- partial matvec over this warp's h-slice ----
        const unsigned myb = hbase + (unsigned)(buf * 4096 + sl * 2048 + lane * 16);
        unsigned long long a0 = 0ull, a1 = 0ull, a2 = 0ull, a3 = 0ull;
        #pragma unroll
        for (int j = 0; j < 4; j++) {
            unsigned long long hA, hB;
            lds_v2_u64(myb + (unsigned)(j * 512), hA, hB);
            a0 = fma2(w[0][j].x, hA, a0);  a0 = fma2(w[0][j].y, hB, a0);
            a1 = fma2(w[1][j].x, hA, a1);  a1 = fma2(w[1][j].y, hB, a1);
            a2 = fma2(w[2][j].x, hA, a2);  a2 = fma2(w[2][j].y, hB, a2);
            a3 = fma2(w[3][j].x, hA, a3);  a3 = fma2(w[3][j].y, hB, a3);
        }
        float s0 = f2sum(a0), s1 = f2sum(a1), s2 = f2sum(a2), s3 = f2sum(a3);
        #pragma unroll
        for (int off = 16; off; off >>= 1) {
            s0 += __shfl_xor_sync(0xffffffffu, s0, off);
            s1 += __shfl_xor_sync(0xffffffffu, s1, off);
            s2 += __shfl_xor_sync(0xffffffffu, s2, off);
            s3 += __shfl_xor_sync(0xffffffffu, s3, off);
        }
        if (lane == 0) {
            const unsigned long long tg = ((unsigned long long)(unsigned)(t + 1)) << 32;
            const unsigned ga = gpbase + (unsigned)((sl * 32 + rg * 4) * 8);
            sts_vol_u64(ga,      tg | (unsigned long long)__float_as_uint(s0));
            sts_vol_u64(ga + 8,  tg | (unsigned long long)__float_as_uint(s1));
            sts_vol_u64(ga + 16, tg | (unsigned long long)__float_as_uint(s2));
            sts_vol_u64(ga + 24, tg | (unsigned long long)__float_as_uint(s3));
        }

        // ---- nonlinearity + publish (8 lanes of warp 0) ----
        if (tid < 8) {
            const unsigned tag = (unsigned)(t + 1);
            float gsum[4];
            #pragma unroll
            for (int g = 0; g < 4; g++) {
                int rl = g * 8 + tid;
                unsigned a0a = gpbase + (unsigned)(rl * 8);
                unsigned a1a = a0a + 256;   // slice-1 bank
                unsigned long long p0 = lds_vol_u64(a0a);
                while ((unsigned)(p0 >> 32) != tag) p0 = lds_vol_u64(a0a);
                unsigned long long p1 = lds_vol_u64(a1a);
                while ((unsigned)(p1 >> 32) != tag) p1 = lds_vol_u64(a1a);
                gsum[g] = __uint_as_float((unsigned)p0) + __uint_as_float((unsigned)p1)
                          + xg4[g];
            }
            float i_ = sigf(gsum[0]);
            float f_ = sigf(gsum[1]);
            float g_ = tanh_acc(gsum[2]);
            float o_ = sigf(gsum[3]);
            c_state = f_ * c_state + i_ * g_;
            float hv = o_ * tanh_acc(c_state);

            float hv1 = __shfl_down_sync(0x000000FFu, hv, 1);
            if ((tid & 1) == 0) {
                __half2 p = __floats2half2_rn(hv, hv1);
                unsigned pu = *(unsigned*)&p;
                unsigned long long pv =
                    (((unsigned long long)tag) << 32) | (unsigned long long)pu;
                st_relaxed_u64(&g_hpack[(t + 1) & 1][cta * 4 + (tid >> 1)], pv);
            }
            out[(size_t)t * HDIM + cta * 8 + tid] = hv;
        }
        // No second barrier: h_sm is double-buffered; buffer reuse at t+2 is
        // ordered by the publish->poll chain (poll t+2 success implies all warps
        // of every CTA completed matvec t+1, hence all reads of buffer t).
    }
}

extern "C" void kernel_launch(void* const* d_in, const int* in_sizes, int n_in,
                              void* d_out, int out_size) {
    const float* x   = (const float*)d_in[0];
    const float* Wih = (const float*)d_in[1];
    const float* Whh = (const float*)d_in[2];
    const float* bih = (const float*)d_in[3];
    const float* bhh = (const float*)d_in[4];
    float* out = (float*)d_out;
    const int N = out_size / HDIM;

    xgates_kernel<<<512, 256>>>(x, Wih, bih, bhh);
    lstm_kernel<<<NCTA, TPB>>>(Whh, out, N);
}